// round 4
// baseline (speedup 1.0000x reference)
#include <cuda_runtime.h>
#include <math.h>

#define TPB    256
#define NWARP  (TPB / 32)
#define MAXM   4096

// Precomputed GT data (filled by prep_kernel):
// gA[j] = (cx, cy, enclosing_radius, area)
// gB[j] = (cos, sin, hx, hy)
__device__ float4 g_gtA[MAXM];
__device__ float4 g_gtB[MAXM];

// Prep: zero output + precompute GT SoA (one launch, trivial).
__global__ void prep_kernel(const float* __restrict__ box_gt, int M,
                            float* __restrict__ out, int out_size) {
    int j = blockIdx.x * blockDim.x + threadIdx.x;
    if (j < out_size) out[j] = 0.0f;
    if (j < M) {
        const float* b = box_gt + j * 7;
        float x = b[0], y = b[1], dx = b[3], dy = b[4], yaw = b[6];
        float s, c;
        __sincosf(yaw, &s, &c);
        g_gtA[j] = make_float4(x, y, 0.5f * sqrtf(dx * dx + dy * dy), dx * dy);
        g_gtB[j] = make_float4(c, s, 0.5f * dx, 0.5f * dy);
    }
}

// Branchless Liang-Barsky segment clip vs box [-hx,hx]x[-hy,hy] (B-local
// param frame); endpoints evaluated in the common o_B-relative frame.
__device__ __forceinline__ float seg_contrib(
    float px, float py, float dx, float dy, float hx, float hy,
    float pwx, float pwy, float dwx, float dwy)
{
    float ix = __fdividef(1.0f, dx);
    float ta = (-hx - px) * ix, tb = (hx - px) * ix;
    float t0 = fmaxf(0.0f, fminf(ta, tb));
    float t1 = fminf(1.0f, fmaxf(ta, tb));
    float iy = __fdividef(1.0f, dy);
    float tc = (-hy - py) * iy, td = (hy - py) * iy;
    t0 = fmaxf(t0, fminf(tc, td));
    t1 = fminf(t1, fmaxf(tc, td));

    float sx = fmaf(t0, dwx, pwx), sy = fmaf(t0, dwy, pwy);
    float ex = fmaf(t1, dwx, pwx), ey = fmaf(t1, dwy, pwy);
    float cr = sx * ey - sy * ex;
    return (t1 >= t0) ? cr : 0.0f;
}

// Task decomposition: task = pred*2 + half. Each warp scans one half of the
// GT set for one pred. NWARP tasks per block -> NWARP/2 preds per block.
__global__ void __launch_bounds__(TPB)
iou_loss_kernel(const float* __restrict__ iou_pred,
                const float* __restrict__ box_pred,
                const void* __restrict__ ntp_raw,
                float* __restrict__ out,
                int N, int M)
{
    __shared__ unsigned short q[NWARP][260];   // per-warp survivor queue
    __shared__ float bests[NWARP];

    const int tid   = threadIdx.x;
    const int lane  = tid & 31;
    const int wslot = tid >> 5;
    const int task  = blockIdx.x * NWARP + wslot;
    const int pred  = task >> 1;
    const int half  = task & 1;

    float best = 0.0f;
    float hax = 0.f, hay = 0.f, sa = 0.f, ca = 1.f, area_a = 0.f;
    float px_ = 0.f, py_ = 0.f;
    float wx[4], wy[4];

    if (pred < N) {
        const float* pb = box_pred + pred * 7;
        px_ = pb[0]; py_ = pb[1];
        hax = 0.5f * pb[3]; hay = 0.5f * pb[4];
        __sincosf(pb[6], &sa, &ca);
        area_a = 4.0f * hax * hay;
        const float ra = sqrtf(hax * hax + hay * hay);

        // A corners (world, CCW)
        {
            const float lx[4] = {hax, -hax, -hax, hax};
            const float ly[4] = {hay, hay, -hay, -hay};
            #pragma unroll
            for (int k = 0; k < 4; k++) {
                wx[k] = px_ + ca * lx[k] - sa * ly[k];
                wy[k] = py_ + sa * lx[k] + ca * ly[k];
            }
        }

        const int Mh   = M >> 1;
        const int jbeg = half ? Mh : 0;
        const int jend = half ? M  : Mh;

        // ---- Phase 1: circle-test scan, warp-compact survivors ----
        int cnt = 0;
        for (int j = jbeg + lane; ; j += 32) {
            bool ok = false;
            if (j < jend) {
                float4 A4 = __ldg(&g_gtA[j]);
                float ddx = A4.x - px_, ddy = A4.y - py_;
                float rr = ra + A4.z;
                ok = (ddx * ddx + ddy * ddy <= rr * rr);
            }
            unsigned m = __ballot_sync(0xffffffffu, ok);
            if (ok) q[wslot][cnt + __popc(m & ((1u << lane) - 1u))] =
                        (unsigned short)j;
            cnt += __popc(m);
            if (j - lane + 32 >= jend) break;
        }

        // ---- Phase 2: dense branchless clip over survivors ----
        for (int k = lane; k < cnt; k += 32) {
            int j = q[wslot][k];
            float4 A4 = __ldg(&g_gtA[j]);
            float4 B4 = __ldg(&g_gtB[j]);
            float bx = A4.x, by = A4.y, area_b = A4.w;
            float cb = B4.x, sb = B4.y, hbx = B4.z, hby = B4.w;

            // A corners rel to o_B (common frame) and in B-local frame
            float rax[4], ray[4], lax[4], lay[4];
            #pragma unroll
            for (int kk = 0; kk < 4; kk++) {
                rax[kk] = wx[kk] - bx;
                ray[kk] = wy[kk] - by;
                lax[kk] =  cb * rax[kk] + sb * ray[kk];
                lay[kk] = -sb * rax[kk] + cb * ray[kk];
            }

            float total = 0.0f;
            #pragma unroll
            for (int kk = 0; kk < 4; kk++) {
                int kn = (kk + 1) & 3;
                total += seg_contrib(lax[kk], lay[kk],
                                     lax[kn] - lax[kk], lay[kn] - lay[kk],
                                     hbx, hby,
                                     rax[kk], ray[kk],
                                     rax[kn] - rax[kk], ray[kn] - ray[kk]);
            }

            // B corners: rel-world (rel to o_B) and in A-local frame
            const float lbx[4] = {hbx, -hbx, -hbx, hbx};
            const float lby[4] = {hby, hby, -hby, -hby};
            float rbx[4], rby[4], qx[4], qy[4];
            float ox = bx - px_, oy = by - py_;
            #pragma unroll
            for (int kk = 0; kk < 4; kk++) {
                rbx[kk] = cb * lbx[kk] - sb * lby[kk];
                rby[kk] = sb * lbx[kk] + cb * lby[kk];
                float tx = rbx[kk] + ox, ty = rby[kk] + oy;
                qx[kk] =  ca * tx + sa * ty;
                qy[kk] = -sa * tx + ca * ty;
            }
            #pragma unroll
            for (int kk = 0; kk < 4; kk++) {
                int kn = (kk + 1) & 3;
                total += seg_contrib(qx[kk], qy[kk],
                                     qx[kn] - qx[kk], qy[kn] - qy[kk],
                                     hax, hay,
                                     rbx[kk], rby[kk],
                                     rbx[kn] - rbx[kk], rby[kn] - rby[kk]);
            }

            float inter = 0.5f * fabsf(total);
            float uni = fmaxf(area_a + area_b - inter, 1e-8f);
            best = fmaxf(best, inter / uni);
        }
    }

    // Warp max reduction -> shared
    #pragma unroll
    for (int o = 16; o > 0; o >>= 1)
        best = fmaxf(best, __shfl_xor_sync(0xffffffffu, best, o));
    if (lane == 0) bests[wslot] = best;
    __syncthreads();

    // Warp 0: combine pred halves (NWARP/2 preds per block), sum terms.
    if (wslot == 0) {
        float term = 0.0f;
        if (lane < NWARP / 2) {
            int p = blockIdx.x * (NWARP / 2) + lane;
            if (p < N) {
                float mx = fmaxf(bests[2 * lane], bests[2 * lane + 1]);
                float target = 2.0f * mx - 1.0f;
                term = fabsf(__ldg(&iou_pred[p]) - target);
            }
        }
        #pragma unroll
        for (int o = 16; o > 0; o >>= 1)
            term += __shfl_xor_sync(0xffffffffu, term, o);
        if (lane == 0 && term != 0.0f) {
            int iv = *(const int*)ntp_raw;
            float fv = __int_as_float(iv);
            float ntp = (iv > 0 && iv < 100000000) ? (float)iv : fv;
            atomicAdd(out, term / (ntp + 1e-4f));
        }
    }
}

extern "C" void kernel_launch(void* const* d_in, const int* in_sizes, int n_in,
                              void* d_out, int out_size) {
    const float* iou_pred = (const float*)d_in[0];
    const float* box_pred = (const float*)d_in[1];
    const float* box_gt   = (const float*)d_in[2];
    const void*  ntp      = d_in[3];

    int N = in_sizes[1] / 7;
    int M = in_sizes[2] / 7;
    if (M > MAXM) M = MAXM;

    float* out = (float*)d_out;

    int pt = 256;
    int pn = M > out_size ? M : out_size;
    prep_kernel<<<(pn + pt - 1) / pt, pt>>>(box_gt, M, out, out_size);

    int tasks = 2 * N;                       // pred x half
    int grid = (tasks + NWARP - 1) / NWARP;  // 512 blocks for N=2048
    iou_loss_kernel<<<grid, TPB>>>(iou_pred, box_pred, ntp, out, N, M);
}